// round 1
// baseline (speedup 1.0000x reference)
#include <cuda_runtime.h>
#include <math_constants.h>

#define BB 4
#define SS 2048
#define DD 1024
#define MM (BB*SS)          // 8192 rows
#define NCHUNK 32
#define CHUNKLEN (SS/NCHUNK) // 64

// ---------------- scratch (static device memory; no allocations) -------------
__device__ float  g_qkv[3][MM][DD];                 // Q,K,V fp32  (96 MB)
__device__ float2 g_spec[3][(size_t)MM * DD];       // FQ,FK,FV complex (192 MB); FQ reused as FOUT
__device__ float2 g_chunk[BB][NCHUNK][DD];          // per-chunk partial sums (1 MB)

// ---------------- GEMM: Y = X * W^T  (both row-major, K contiguous) ----------
// BM=BN=128, BK=16, 256 threads, 8x8 per-thread microtile
__global__ __launch_bounds__(256) void gemm_xwt(
    const float* __restrict__ X,
    const float* __restrict__ Wq,
    const float* __restrict__ Wk,
    const float* __restrict__ Wv)
{
    const int which = blockIdx.z;
    const float* __restrict__ W = (which == 0) ? Wq : (which == 1) ? Wk : Wv;
    float* __restrict__ Y = &g_qkv[which][0][0];

    __shared__ float As[16][132];   // As[k][m], padded
    __shared__ float Bs[16][132];   // Bs[k][n], padded

    const int tid = threadIdx.x;
    const int m0 = blockIdx.y * 128;
    const int n0 = blockIdx.x * 128;
    const int tm = (tid / 16) * 8;
    const int tn = (tid % 16) * 8;

    float acc[8][8];
#pragma unroll
    for (int i = 0; i < 8; i++)
#pragma unroll
        for (int j = 0; j < 8; j++) acc[i][j] = 0.f;

    for (int k0 = 0; k0 < DD; k0 += 16) {
        // load X tile (128 rows x 16 cols) -> As[k][m]
#pragma unroll
        for (int it = 0; it < 2; it++) {
            int idx = tid + it * 256;        // 0..511
            int r = idx >> 2;                // row within tile
            int c4 = idx & 3;                // which float4 of the 16-wide strip
            float4 v = *(const float4*)&X[(size_t)(m0 + r) * DD + k0 + c4 * 4];
            As[c4 * 4 + 0][r] = v.x;
            As[c4 * 4 + 1][r] = v.y;
            As[c4 * 4 + 2][r] = v.z;
            As[c4 * 4 + 3][r] = v.w;
        }
        // load W tile (128 N-rows x 16 cols) -> Bs[k][n]
#pragma unroll
        for (int it = 0; it < 2; it++) {
            int idx = tid + it * 256;
            int r = idx >> 2;
            int c4 = idx & 3;
            float4 v = *(const float4*)&W[(size_t)(n0 + r) * DD + k0 + c4 * 4];
            Bs[c4 * 4 + 0][r] = v.x;
            Bs[c4 * 4 + 1][r] = v.y;
            Bs[c4 * 4 + 2][r] = v.z;
            Bs[c4 * 4 + 3][r] = v.w;
        }
        __syncthreads();

#pragma unroll
        for (int k = 0; k < 16; k++) {
            float4 a0 = *(const float4*)&As[k][tm];
            float4 a1 = *(const float4*)&As[k][tm + 4];
            float4 b0 = *(const float4*)&Bs[k][tn];
            float4 b1 = *(const float4*)&Bs[k][tn + 4];
            float a[8] = {a0.x, a0.y, a0.z, a0.w, a1.x, a1.y, a1.z, a1.w};
            float b[8] = {b0.x, b0.y, b0.z, b0.w, b1.x, b1.y, b1.z, b1.w};
#pragma unroll
            for (int i = 0; i < 8; i++)
#pragma unroll
                for (int j = 0; j < 8; j++) acc[i][j] = fmaf(a[i], b[j], acc[i][j]);
        }
        __syncthreads();
    }

#pragma unroll
    for (int i = 0; i < 8; i++) {
        float4 o0 = make_float4(acc[i][0], acc[i][1], acc[i][2], acc[i][3]);
        float4 o1 = make_float4(acc[i][4], acc[i][5], acc[i][6], acc[i][7]);
        *(float4*)&Y[(size_t)(m0 + tm + i) * DD + n0 + tn]     = o0;
        *(float4*)&Y[(size_t)(m0 + tm + i) * DD + n0 + tn + 4] = o1;
    }
}

// ---------------- 1024-point complex FFT (Stockham, shared memory) -----------
// 128 threads, 4 butterflies/thread/stage, 10 stages, auto-sorted output.
__device__ __forceinline__ void fft1024_shared(float2* bufA, float2* bufB)
{
    const int t = threadIdx.x;
    float2* x = bufA;
    float2* y = bufB;
    int l = 512, m = 1;
#pragma unroll 1
    for (int s = 0; s < 10; s++) {
#pragma unroll
        for (int q = 0; q < 4; q++) {
            int bf = t + q * 128;          // 0..511
            int j = bf / m;                // m is power of two -> shift
            int k = bf - j * m;
            float ang = -(float)CUDART_PI_F * (float)j / (float)l;
            float sn, cs;
            __sincosf(ang, &sn, &cs);
            float2 c0 = x[k + j * m];
            float2 c1 = x[k + j * m + 512];
            float2 sum = make_float2(c0.x + c1.x, c0.y + c1.y);
            float2 dif = make_float2(c0.x - c1.x, c0.y - c1.y);
            y[k + 2 * j * m]     = sum;
            y[k + 2 * j * m + m] = make_float2(cs * dif.x - sn * dif.y,
                                               cs * dif.y + sn * dif.x);
        }
        __syncthreads();
        float2* tmp = x; x = y; y = tmp;
        l >>= 1; m <<= 1;
    }
    // after even number of swaps, result resides in bufA
}

// forward FFT of real rows of g_qkv -> g_spec
__global__ __launch_bounds__(128) void fft_fwd()
{
    __shared__ float2 bufA[1024];
    __shared__ float2 bufB[1024];
    const int which = blockIdx.y;
    const int row = blockIdx.x;
    const float* __restrict__ src = &g_qkv[which][row][0];
    float2* __restrict__ dst = &g_spec[which][(size_t)row * DD];
    const int t = threadIdx.x;
#pragma unroll
    for (int i = 0; i < 8; i++) {
        int idx = t + i * 128;
        bufA[idx] = make_float2(src[idx], 0.f);
    }
    __syncthreads();
    fft1024_shared(bufA, bufB);
#pragma unroll
    for (int i = 0; i < 8; i++) {
        int idx = t + i * 128;
        dst[idx] = bufA[idx];
    }
}

// inverse FFT of g_spec[0] (=FOUT) -> real output; ifft(X).real = Re(FFT(conj X))/N
__global__ __launch_bounds__(128) void fft_inv(float* __restrict__ out)
{
    __shared__ float2 bufA[1024];
    __shared__ float2 bufB[1024];
    const int row = blockIdx.x;
    const float2* __restrict__ src = &g_spec[0][(size_t)row * DD];
    float* __restrict__ dst = &out[(size_t)row * DD];
    const int t = threadIdx.x;
#pragma unroll
    for (int i = 0; i < 8; i++) {
        int idx = t + i * 128;
        float2 v = src[idx];
        bufA[idx] = make_float2(v.x, -v.y);
    }
    __syncthreads();
    fft1024_shared(bufA, bufB);
    const float invn = 1.f / 1024.f;
#pragma unroll
    for (int i = 0; i < 8; i++) {
        int idx = t + i * 128;
        dst[idx] = bufA[idx].x * invn;
    }
}

// ---------------- causal scan of fk*fv, unbind with conj(fq) -----------------
// phase A: per-chunk totals of fk*fv
__global__ __launch_bounds__(128) void scanA()
{
    const int chunk = blockIdx.x;
    const int dt = blockIdx.y;
    const int b = blockIdx.z;
    const int d = dt * 128 + threadIdx.x;
    size_t base = ((size_t)b * SS + (size_t)chunk * CHUNKLEN) * DD + d;
    float2 acc = make_float2(0.f, 0.f);
#pragma unroll 4
    for (int s = 0; s < CHUNKLEN; s++) {
        float2 fk = g_spec[1][base + (size_t)s * DD];
        float2 fv = g_spec[2][base + (size_t)s * DD];
        acc.x += fk.x * fv.x - fk.y * fv.y;
        acc.y += fk.x * fv.y + fk.y * fv.x;
    }
    g_chunk[b][chunk][d] = acc;
}

// phase C: running sum within chunk (+ prefix of prior chunks), fout = mem*conj(fq)
__global__ __launch_bounds__(128) void scanC()
{
    const int chunk = blockIdx.x;
    const int dt = blockIdx.y;
    const int b = blockIdx.z;
    const int d = dt * 128 + threadIdx.x;
    size_t base = ((size_t)b * SS + (size_t)chunk * CHUNKLEN) * DD + d;
    float2 acc = make_float2(0.f, 0.f);
    for (int c = 0; c < chunk; c++) {
        float2 p = g_chunk[b][c][d];
        acc.x += p.x; acc.y += p.y;
    }
#pragma unroll 4
    for (int s = 0; s < CHUNKLEN; s++) {
        float2 fk = g_spec[1][base + (size_t)s * DD];
        float2 fv = g_spec[2][base + (size_t)s * DD];
        acc.x += fk.x * fv.x - fk.y * fv.y;
        acc.y += fk.x * fv.y + fk.y * fv.x;
        float2 fq = g_spec[0][base + (size_t)s * DD];
        // mem * conj(fq)
        float2 o = make_float2(acc.x * fq.x + acc.y * fq.y,
                               acc.y * fq.x - acc.x * fq.y);
        g_spec[0][base + (size_t)s * DD] = o;   // overwrite FQ as FOUT
    }
}

// ---------------- launch ------------------------------------------------------
extern "C" void kernel_launch(void* const* d_in, const int* in_sizes, int n_in,
                              void* d_out, int out_size)
{
    const float* x  = (const float*)d_in[0];
    const float* Wq = (const float*)d_in[1];
    const float* Wk = (const float*)d_in[2];
    const float* Wv = (const float*)d_in[3];
    float* out = (float*)d_out;

    dim3 ggrid(DD / 128, MM / 128, 3);      // (8, 64, 3)
    gemm_xwt<<<ggrid, 256>>>(x, Wq, Wk, Wv);

    dim3 fgrid(MM, 3);
    fft_fwd<<<fgrid, 128>>>();

    dim3 sgrid(NCHUNK, DD / 128, BB);       // (32, 8, 4)
    scanA<<<sgrid, 128>>>();
    scanC<<<sgrid, 128>>>();

    fft_inv<<<MM, 128>>>(out);
}

// round 3
// speedup vs baseline: 2.0381x; 2.0381x over previous
#include <cuda_runtime.h>
#include <cuda_bf16.h>
#include <math_constants.h>
#include <cstdint>

#define BB 4
#define SS 2048
#define DD 1024
#define MM (BB*SS)          // 8192 rows
#define NCHUNK 32
#define CHUNKLEN (SS/NCHUNK) // 64

// GEMM tiling
#define MT 128
#define NT 128
#define KC 64
#define NKCH (DD/KC)        // 16

// ---------------- scratch (static device memory; no allocations) -------------
__device__ float  g_qkv[3][MM][DD];                 // Q,K,V fp32  (96 MB)
__device__ float2 g_spec[3][(size_t)MM * DD];       // FQ,FK,FV complex (192 MB); FQ reused as FOUT
__device__ float2 g_chunk[BB][NCHUNK][DD];          // per-chunk partial sums (1 MB)
__device__ __nv_bfloat16 g_xhi[(size_t)MM * DD];    // 16 MB
__device__ __nv_bfloat16 g_xlo[(size_t)MM * DD];    // 16 MB
__device__ __nv_bfloat16 g_whi[3][DD * DD];         // 6 MB
__device__ __nv_bfloat16 g_wlo[3][DD * DD];         // 6 MB

// ---------------- PTX helpers -------------------------------------------------
__device__ __forceinline__ uint32_t smem_u32(const void* p) {
    uint32_t a;
    asm("{ .reg .u64 t; cvta.to.shared.u64 t, %1; cvt.u32.u64 %0, t; }" : "=r"(a) : "l"(p));
    return a;
}
__device__ __forceinline__ void cp16(uint32_t dst, const void* src) {
    asm volatile("cp.async.cg.shared.global [%0], [%1], 16;" :: "r"(dst), "l"(src) : "memory");
}
__device__ __forceinline__ void cp_commit() { asm volatile("cp.async.commit_group;" ::: "memory"); }
__device__ __forceinline__ void cp_wait1()  { asm volatile("cp.async.wait_group 1;" ::: "memory"); }
__device__ __forceinline__ void cp_wait0()  { asm volatile("cp.async.wait_group 0;" ::: "memory"); }

__device__ __forceinline__ void ldsm4(uint32_t* r, uint32_t addr) {
    asm volatile("ldmatrix.sync.aligned.m8n8.x4.shared.b16 {%0,%1,%2,%3}, [%4];"
        : "=r"(r[0]), "=r"(r[1]), "=r"(r[2]), "=r"(r[3]) : "r"(addr));
}
__device__ __forceinline__ void hmma(float* c, const uint32_t* a, const uint32_t* b) {
    asm volatile("mma.sync.aligned.m16n8k16.row.col.f32.bf16.bf16.f32 "
        "{%0,%1,%2,%3}, {%4,%5,%6,%7}, {%8,%9}, {%0,%1,%2,%3};"
        : "+f"(c[0]), "+f"(c[1]), "+f"(c[2]), "+f"(c[3])
        : "r"(a[0]), "r"(a[1]), "r"(a[2]), "r"(a[3]), "r"(b[0]), "r"(b[1]));
}

// ---------------- hi/lo bf16 split kernels ------------------------------------
__device__ __forceinline__ unsigned short bfu(float f) {
    __nv_bfloat16 h = __float2bfloat16(f);
    return *reinterpret_cast<unsigned short*>(&h);
}
__device__ __forceinline__ float bff(unsigned short u) {
    __nv_bfloat16 h;
    *reinterpret_cast<unsigned short*>(&h) = u;
    return __bfloat162float(h);
}
__device__ __forceinline__ void split4(float4 v, ushort4& H, ushort4& L) {
    H.x = bfu(v.x); L.x = bfu(v.x - bff(H.x));
    H.y = bfu(v.y); L.y = bfu(v.y - bff(H.y));
    H.z = bfu(v.z); L.z = bfu(v.z - bff(H.z));
    H.w = bfu(v.w); L.w = bfu(v.w - bff(H.w));
}

__global__ __launch_bounds__(256) void split_x_k(const float* __restrict__ X) {
    size_t i = ((size_t)blockIdx.x * 256 + threadIdx.x) * 4;
    float4 v = *(const float4*)(X + i);
    ushort4 H, L;
    split4(v, H, L);
    *(ushort4*)&g_xhi[i] = H;
    *(ushort4*)&g_xlo[i] = L;
}

__global__ __launch_bounds__(256) void split_w_k(const float* __restrict__ Wq,
                                                 const float* __restrict__ Wk,
                                                 const float* __restrict__ Wv) {
    const int which = blockIdx.y;
    const float* __restrict__ W = (which == 0) ? Wq : (which == 1) ? Wk : Wv;
    size_t i = ((size_t)blockIdx.x * 256 + threadIdx.x) * 4;
    float4 v = *(const float4*)(W + i);
    ushort4 H, L;
    split4(v, H, L);
    *(ushort4*)&g_whi[which][i] = H;
    *(ushort4*)&g_wlo[which][i] = L;
}

// ---------------- HMMA GEMM: Y = X * W^T  (bf16 hi/lo split, fp32 accum) ------
// 256 threads = 8 warps (4m x 2n), warp tile 32x64, mma m16n8k16
#define GSM_BUF   65536
#define OFF_AHI   0
#define OFF_ALO   16384
#define OFF_BHI   32768
#define OFF_BLO   49152
#define GEMM_SMEM_BYTES (133 * 1024)

__device__ __forceinline__ uint32_t sw128(uint32_t bo) {
    return bo ^ ((bo >> 3) & 0x70);
}

__device__ __forceinline__ void load_chunk(uint32_t sb, int buf, int ch, int m0, int n0, int tid,
                                           const __nv_bfloat16* __restrict__ Ah,
                                           const __nv_bfloat16* __restrict__ Al,
                                           const __nv_bfloat16* __restrict__ Bh,
                                           const __nv_bfloat16* __restrict__ Bl) {
    const int c0 = ch * KC;
    const uint32_t base = sb + buf * GSM_BUF;
#pragma unroll
    for (int i = 0; i < 4; i++) {
        int seg = tid + i * 256;        // 0..1023 : 16B segments of a 128x128B tile
        int row = seg >> 3;
        int sc  = seg & 7;
        uint32_t sw = sw128((uint32_t)(row * 128 + sc * 16));
        size_t ga = (size_t)(m0 + row) * DD + c0 + sc * 8;
        size_t gb = (size_t)(n0 + row) * DD + c0 + sc * 8;
        cp16(base + OFF_AHI + sw, Ah + ga);
        cp16(base + OFF_ALO + sw, Al + ga);
        cp16(base + OFF_BHI + sw, Bh + gb);
        cp16(base + OFF_BLO + sw, Bl + gb);
    }
}

__global__ __launch_bounds__(256) void gemm_hmma() {
    extern __shared__ __align__(16) char smem_raw[];
    uint32_t raw = smem_u32(smem_raw);
    uint32_t sb = (raw + 1023) & ~1023u;   // 1KB-align for clean SW128 banking

    const int tid = threadIdx.x;
    const int wid = tid >> 5;
    const int l   = tid & 31;
    const int which = blockIdx.z;
    const int m0 = blockIdx.y * MT;
    const int n0 = blockIdx.x * NT;
    const int warp_m = (wid & 3) * 32;
    const int warp_n = (wid >> 2) * 64;

    const __nv_bfloat16* __restrict__ Ah = g_xhi;
    const __nv_bfloat16* __restrict__ Al = g_xlo;
    const __nv_bfloat16* __restrict__ Bh = g_whi[which];
    const __nv_bfloat16* __restrict__ Bl = g_wlo[which];
    float* __restrict__ Y = &g_qkv[which][0][0];

    float acc[2][8][4];
#pragma unroll
    for (int i = 0; i < 2; i++)
#pragma unroll
        for (int j = 0; j < 8; j++)
#pragma unroll
            for (int k = 0; k < 4; k++) acc[i][j][k] = 0.f;

    // precomputed intra-tile ldmatrix address components
    // A: lanes 0-15 -> rows m+(l&15) at kseg lo, lanes 16-31 same rows at kseg hi
    const int a_row = (l & 15);
    const int a_k16 = (l >> 4);            // 0 or 1 (which 8-col block)
    // B: lanes 0-7 n0..7@k0, 8-15 n0..7@k8, 16-23 n8..15@k0, 24-31 n8..15@k8
    const int b_row = (l & 7) + ((l >> 4) & 1) * 8;
    const int b_k16 = (l >> 3) & 1;

    load_chunk(sb, 0, 0, m0, n0, tid, Ah, Al, Bh, Bl);
    cp_commit();

    for (int c = 0; c < NKCH; c++) {
        if (c + 1 < NKCH) {
            load_chunk(sb, (c + 1) & 1, c + 1, m0, n0, tid, Ah, Al, Bh, Bl);
            cp_commit();
            cp_wait1();
        } else {
            cp_wait0();
        }
        __syncthreads();

        const uint32_t base = sb + (c & 1) * GSM_BUF;
#pragma unroll
        for (int ks = 0; ks < 4; ks++) {
            uint32_t ah[2][4], al[2][4], bh[8][2], bl[8][2];
#pragma unroll
            for (int mt = 0; mt < 2; mt++) {
                uint32_t bo = (uint32_t)((warp_m + mt * 16 + a_row) * 128 + (ks * 2 + a_k16) * 16);
                uint32_t sw = sw128(bo);
                ldsm4(ah[mt], base + OFF_AHI + sw);
                ldsm4(al[mt], base + OFF_ALO + sw);
            }
#pragma unroll
            for (int p = 0; p < 4; p++) {
                uint32_t bo = (uint32_t)((warp_n + p * 16 + b_row) * 128 + (ks * 2 + b_k16) * 16);
                uint32_t sw = sw128(bo);
                uint32_t r[4];
                ldsm4(r, base + OFF_BHI + sw);
                bh[2 * p][0] = r[0]; bh[2 * p][1] = r[1];
                bh[2 * p + 1][0] = r[2]; bh[2 * p + 1][1] = r[3];
                ldsm4(r, base + OFF_BLO + sw);
                bl[2 * p][0] = r[0]; bl[2 * p][1] = r[1];
                bl[2 * p + 1][0] = r[2]; bl[2 * p + 1][1] = r[3];
            }
#pragma unroll
            for (int mt = 0; mt < 2; mt++)
#pragma unroll
                for (int nt = 0; nt < 8; nt++) {
                    hmma(acc[mt][nt], ah[mt], bh[nt]);
                    hmma(acc[mt][nt], ah[mt], bl[nt]);
                    hmma(acc[mt][nt], al[mt], bh[nt]);
                }
        }
        __syncthreads();
    }

    // epilogue: direct fragment stores (float2 per half-tile)
    const int g = l >> 2;
    const int t = l & 3;
#pragma unroll
    for (int mt = 0; mt < 2; mt++)
#pragma unroll
        for (int nt = 0; nt < 8; nt++) {
            int m = m0 + warp_m + mt * 16 + g;
            int n = n0 + warp_n + nt * 8 + t * 2;
            *(float2*)&Y[(size_t)m * DD + n]       = make_float2(acc[mt][nt][0], acc[mt][nt][1]);
            *(float2*)&Y[(size_t)(m + 8) * DD + n] = make_float2(acc[mt][nt][2], acc[mt][nt][3]);
        }
}

// ---------------- 1024-point complex FFT (Stockham, shared memory) -----------
__device__ __forceinline__ void fft1024_shared(float2* bufA, float2* bufB)
{
    const int t = threadIdx.x;
    float2* x = bufA;
    float2* y = bufB;
    int l = 512, m = 1;
#pragma unroll 1
    for (int s = 0; s < 10; s++) {
#pragma unroll
        for (int q = 0; q < 4; q++) {
            int bf = t + q * 128;
            int j = bf / m;
            int k = bf - j * m;
            float ang = -(float)CUDART_PI_F * (float)j / (float)l;
            float sn, cs;
            __sincosf(ang, &sn, &cs);
            float2 c0 = x[k + j * m];
            float2 c1 = x[k + j * m + 512];
            float2 sum = make_float2(c0.x + c1.x, c0.y + c1.y);
            float2 dif = make_float2(c0.x - c1.x, c0.y - c1.y);
            y[k + 2 * j * m]     = sum;
            y[k + 2 * j * m + m] = make_float2(cs * dif.x - sn * dif.y,
                                               cs * dif.y + sn * dif.x);
        }
        __syncthreads();
        float2* tmp = x; x = y; y = tmp;
        l >>= 1; m <<= 1;
    }
}

__global__ __launch_bounds__(128) void fft_fwd()
{
    __shared__ float2 bufA[1024];
    __shared__ float2 bufB[1024];
    const int which = blockIdx.y;
    const int row = blockIdx.x;
    const float* __restrict__ src = &g_qkv[which][row][0];
    float2* __restrict__ dst = &g_spec[which][(size_t)row * DD];
    const int t = threadIdx.x;
#pragma unroll
    for (int i = 0; i < 8; i++) {
        int idx = t + i * 128;
        bufA[idx] = make_float2(src[idx], 0.f);
    }
    __syncthreads();
    fft1024_shared(bufA, bufB);
#pragma unroll
    for (int i = 0; i < 8; i++) {
        int idx = t + i * 128;
        dst[idx] = bufA[idx];
    }
}

__global__ __launch_bounds__(128) void fft_inv(float* __restrict__ out)
{
    __shared__ float2 bufA[1024];
    __shared__ float2 bufB[1024];
    const int row = blockIdx.x;
    const float2* __restrict__ src = &g_spec[0][(size_t)row * DD];
    float* __restrict__ dst = &out[(size_t)row * DD];
    const int t = threadIdx.x;
#pragma unroll
    for (int i = 0; i < 8; i++) {
        int idx = t + i * 128;
        float2 v = src[idx];
        bufA[idx] = make_float2(v.x, -v.y);
    }
    __syncthreads();
    fft1024_shared(bufA, bufB);
    const float invn = 1.f / 1024.f;
#pragma unroll
    for (int i = 0; i < 8; i++) {
        int idx = t + i * 128;
        dst[idx] = bufA[idx].x * invn;
    }
}

// ---------------- causal scan of fk*fv, unbind with conj(fq) -----------------
__global__ __launch_bounds__(128) void scanA()
{
    const int chunk = blockIdx.x;
    const int dt = blockIdx.y;
    const int b = blockIdx.z;
    const int d = dt * 128 + threadIdx.x;
    size_t base = ((size_t)b * SS + (size_t)chunk * CHUNKLEN) * DD + d;
    float2 acc = make_float2(0.f, 0.f);
#pragma unroll 4
    for (int s = 0; s < CHUNKLEN; s++) {
        float2 fk = g_spec[1][base + (size_t)s * DD];
        float2 fv = g_spec[2][base + (size_t)s * DD];
        acc.x += fk.x * fv.x - fk.y * fv.y;
        acc.y += fk.x * fv.y + fk.y * fv.x;
    }
    g_chunk[b][chunk][d] = acc;
}

__global__ __launch_bounds__(128) void scanC()
{
    const int chunk = blockIdx.x;
    const int dt = blockIdx.y;
    const int b = blockIdx.z;
    const int d = dt * 128 + threadIdx.x;
    size_t base = ((size_t)b * SS + (size_t)chunk * CHUNKLEN) * DD + d;
    float2 acc = make_float2(0.f, 0.f);
    for (int c = 0; c < chunk; c++) {
        float2 p = g_chunk[b][c][d];
        acc.x += p.x; acc.y += p.y;
    }
#pragma unroll 4
    for (int s = 0; s < CHUNKLEN; s++) {
        float2 fk = g_spec[1][base + (size_t)s * DD];
        float2 fv = g_spec[2][base + (size_t)s * DD];
        acc.x += fk.x * fv.x - fk.y * fv.y;
        acc.y += fk.x * fv.y + fk.y * fv.x;
        float2 fq = g_spec[0][base + (size_t)s * DD];
        float2 o = make_float2(acc.x * fq.x + acc.y * fq.y,
                               acc.y * fq.x - acc.x * fq.y);
        g_spec[0][base + (size_t)s * DD] = o;
    }
}

// ---------------- launch ------------------------------------------------------
extern "C" void kernel_launch(void* const* d_in, const int* in_sizes, int n_in,
                              void* d_out, int out_size)
{
    const float* x  = (const float*)d_in[0];
    const float* Wq = (const float*)d_in[1];
    const float* Wk = (const float*)d_in[2];
    const float* Wv = (const float*)d_in[3];
    float* out = (float*)d_out;

    split_x_k<<<(MM * DD) / 1024, 256>>>(x);
    split_w_k<<<dim3((DD * DD) / 1024, 3), 256>>>(Wq, Wk, Wv);

    cudaFuncSetAttribute(gemm_hmma, cudaFuncAttributeMaxDynamicSharedMemorySize, GEMM_SMEM_BYTES);
    gemm_hmma<<<dim3(DD / NT, MM / MT, 3), 256, GEMM_SMEM_BYTES>>>();

    fft_fwd<<<dim3(MM, 3), 128>>>();

    dim3 sgrid(NCHUNK, DD / 128, BB);
    scanA<<<sgrid, 128>>>();
    scanC<<<sgrid, 128>>>();

    fft_inv<<<MM, 128>>>(out);
}

// round 4
// speedup vs baseline: 2.3548x; 1.1554x over previous
#include <cuda_runtime.h>
#include <cuda_bf16.h>
#include <math_constants.h>
#include <cstdint>

#define BB 4
#define SS 2048
#define DD 1024
#define MM (BB*SS)          // 8192 rows
#define NCHUNK 32
#define CHUNKLEN (SS/NCHUNK) // 64

// GEMM tiling
#define MT 128
#define NT 128
#define KC 64
#define NKCH (DD/KC)        // 16

// ---------------- scratch (static device memory; no allocations) -------------
__device__ float  g_qkv[3][MM][DD];                 // Q,K,V fp32  (96 MB)
__device__ float2 g_spec[3][(size_t)MM * DD];       // FQ,FK,FV complex (192 MB); FQ reused as FOUT
__device__ float2 g_chunk[BB][NCHUNK][DD];          // per-chunk partial sums (1 MB)
__device__ __nv_bfloat16 g_xhi[(size_t)MM * DD];    // 16 MB
__device__ __nv_bfloat16 g_xlo[(size_t)MM * DD];    // 16 MB
__device__ __nv_bfloat16 g_whi[3][DD * DD];         // 6 MB
__device__ __nv_bfloat16 g_wlo[3][DD * DD];         // 6 MB

// ---------------- PTX helpers -------------------------------------------------
__device__ __forceinline__ uint32_t smem_u32(const void* p) {
    uint32_t a;
    asm("{ .reg .u64 t; cvta.to.shared.u64 t, %1; cvt.u32.u64 %0, t; }" : "=r"(a) : "l"(p));
    return a;
}
__device__ __forceinline__ void cp16(uint32_t dst, const void* src) {
    asm volatile("cp.async.cg.shared.global [%0], [%1], 16;" :: "r"(dst), "l"(src) : "memory");
}
__device__ __forceinline__ void cp_commit() { asm volatile("cp.async.commit_group;" ::: "memory"); }
__device__ __forceinline__ void cp_wait1()  { asm volatile("cp.async.wait_group 1;" ::: "memory"); }
__device__ __forceinline__ void cp_wait0()  { asm volatile("cp.async.wait_group 0;" ::: "memory"); }

__device__ __forceinline__ void ldsm4(uint32_t* r, uint32_t addr) {
    asm volatile("ldmatrix.sync.aligned.m8n8.x4.shared.b16 {%0,%1,%2,%3}, [%4];"
        : "=r"(r[0]), "=r"(r[1]), "=r"(r[2]), "=r"(r[3]) : "r"(addr));
}
__device__ __forceinline__ void hmma(float* c, const uint32_t* a, const uint32_t* b) {
    asm volatile("mma.sync.aligned.m16n8k16.row.col.f32.bf16.bf16.f32 "
        "{%0,%1,%2,%3}, {%4,%5,%6,%7}, {%8,%9}, {%0,%1,%2,%3};"
        : "+f"(c[0]), "+f"(c[1]), "+f"(c[2]), "+f"(c[3])
        : "r"(a[0]), "r"(a[1]), "r"(a[2]), "r"(a[3]), "r"(b[0]), "r"(b[1]));
}

// ---------------- hi/lo bf16 split kernels ------------------------------------
__device__ __forceinline__ unsigned short bfu(float f) {
    __nv_bfloat16 h = __float2bfloat16(f);
    return *reinterpret_cast<unsigned short*>(&h);
}
__device__ __forceinline__ float bff(unsigned short u) {
    __nv_bfloat16 h;
    *reinterpret_cast<unsigned short*>(&h) = u;
    return __bfloat162float(h);
}
__device__ __forceinline__ void split4(float4 v, ushort4& H, ushort4& L) {
    H.x = bfu(v.x); L.x = bfu(v.x - bff(H.x));
    H.y = bfu(v.y); L.y = bfu(v.y - bff(H.y));
    H.z = bfu(v.z); L.z = bfu(v.z - bff(H.z));
    H.w = bfu(v.w); L.w = bfu(v.w - bff(H.w));
}

__global__ __launch_bounds__(256) void split_x_k(const float* __restrict__ X) {
    size_t i = ((size_t)blockIdx.x * 256 + threadIdx.x) * 4;
    float4 v = *(const float4*)(X + i);
    ushort4 H, L;
    split4(v, H, L);
    *(ushort4*)&g_xhi[i] = H;
    *(ushort4*)&g_xlo[i] = L;
}

__global__ __launch_bounds__(256) void split_w_k(const float* __restrict__ Wq,
                                                 const float* __restrict__ Wk,
                                                 const float* __restrict__ Wv) {
    const int which = blockIdx.y;
    const float* __restrict__ W = (which == 0) ? Wq : (which == 1) ? Wk : Wv;
    size_t i = ((size_t)blockIdx.x * 256 + threadIdx.x) * 4;
    float4 v = *(const float4*)(W + i);
    ushort4 H, L;
    split4(v, H, L);
    *(ushort4*)&g_whi[which][i] = H;
    *(ushort4*)&g_wlo[which][i] = L;
}

// ---------------- HMMA GEMM: Y = X * W^T  (bf16 hi/lo split, fp32 accum) ------
#define GSM_BUF   65536
#define OFF_AHI   0
#define OFF_ALO   16384
#define OFF_BHI   32768
#define OFF_BLO   49152
#define GEMM_SMEM_BYTES (133 * 1024)

__device__ __forceinline__ uint32_t sw128(uint32_t bo) {
    return bo ^ ((bo >> 3) & 0x70);
}

__device__ __forceinline__ void load_chunk(uint32_t sb, int buf, int ch, int m0, int n0, int tid,
                                           const __nv_bfloat16* __restrict__ Ah,
                                           const __nv_bfloat16* __restrict__ Al,
                                           const __nv_bfloat16* __restrict__ Bh,
                                           const __nv_bfloat16* __restrict__ Bl) {
    const int c0 = ch * KC;
    const uint32_t base = sb + buf * GSM_BUF;
#pragma unroll
    for (int i = 0; i < 4; i++) {
        int seg = tid + i * 256;
        int row = seg >> 3;
        int sc  = seg & 7;
        uint32_t sw = sw128((uint32_t)(row * 128 + sc * 16));
        size_t ga = (size_t)(m0 + row) * DD + c0 + sc * 8;
        size_t gb = (size_t)(n0 + row) * DD + c0 + sc * 8;
        cp16(base + OFF_AHI + sw, Ah + ga);
        cp16(base + OFF_ALO + sw, Al + ga);
        cp16(base + OFF_BHI + sw, Bh + gb);
        cp16(base + OFF_BLO + sw, Bl + gb);
    }
}

__global__ __launch_bounds__(256) void gemm_hmma() {
    extern __shared__ __align__(16) char smem_raw[];
    uint32_t raw = smem_u32(smem_raw);
    uint32_t sb = (raw + 1023) & ~1023u;

    const int tid = threadIdx.x;
    const int wid = tid >> 5;
    const int l   = tid & 31;
    const int which = blockIdx.z;
    const int m0 = blockIdx.y * MT;
    const int n0 = blockIdx.x * NT;
    const int warp_m = (wid & 3) * 32;
    const int warp_n = (wid >> 2) * 64;

    const __nv_bfloat16* __restrict__ Ah = g_xhi;
    const __nv_bfloat16* __restrict__ Al = g_xlo;
    const __nv_bfloat16* __restrict__ Bh = g_whi[which];
    const __nv_bfloat16* __restrict__ Bl = g_wlo[which];
    float* __restrict__ Y = &g_qkv[which][0][0];

    float acc[2][8][4];
#pragma unroll
    for (int i = 0; i < 2; i++)
#pragma unroll
        for (int j = 0; j < 8; j++)
#pragma unroll
            for (int k = 0; k < 4; k++) acc[i][j][k] = 0.f;

    const int a_row = (l & 15);
    const int a_k16 = (l >> 4);
    const int b_row = (l & 7) + ((l >> 4) & 1) * 8;
    const int b_k16 = (l >> 3) & 1;

    load_chunk(sb, 0, 0, m0, n0, tid, Ah, Al, Bh, Bl);
    cp_commit();

    for (int c = 0; c < NKCH; c++) {
        if (c + 1 < NKCH) {
            load_chunk(sb, (c + 1) & 1, c + 1, m0, n0, tid, Ah, Al, Bh, Bl);
            cp_commit();
            cp_wait1();
        } else {
            cp_wait0();
        }
        __syncthreads();

        const uint32_t base = sb + (c & 1) * GSM_BUF;
#pragma unroll
        for (int ks = 0; ks < 4; ks++) {
            uint32_t ah[2][4], al[2][4], bh[8][2], bl[8][2];
#pragma unroll
            for (int mt = 0; mt < 2; mt++) {
                uint32_t bo = (uint32_t)((warp_m + mt * 16 + a_row) * 128 + (ks * 2 + a_k16) * 16);
                uint32_t sw = sw128(bo);
                ldsm4(ah[mt], base + OFF_AHI + sw);
                ldsm4(al[mt], base + OFF_ALO + sw);
            }
#pragma unroll
            for (int p = 0; p < 4; p++) {
                uint32_t bo = (uint32_t)((warp_n + p * 16 + b_row) * 128 + (ks * 2 + b_k16) * 16);
                uint32_t sw = sw128(bo);
                uint32_t r[4];
                ldsm4(r, base + OFF_BHI + sw);
                bh[2 * p][0] = r[0]; bh[2 * p][1] = r[1];
                bh[2 * p + 1][0] = r[2]; bh[2 * p + 1][1] = r[3];
                ldsm4(r, base + OFF_BLO + sw);
                bl[2 * p][0] = r[0]; bl[2 * p][1] = r[1];
                bl[2 * p + 1][0] = r[2]; bl[2 * p + 1][1] = r[3];
            }
#pragma unroll
            for (int mt = 0; mt < 2; mt++)
#pragma unroll
                for (int nt = 0; nt < 8; nt++) {
                    hmma(acc[mt][nt], ah[mt], bh[nt]);
                    hmma(acc[mt][nt], ah[mt], bl[nt]);
                    hmma(acc[mt][nt], al[mt], bh[nt]);
                }
        }
        __syncthreads();
    }

    const int g = l >> 2;
    const int t = l & 3;
#pragma unroll
    for (int mt = 0; mt < 2; mt++)
#pragma unroll
        for (int nt = 0; nt < 8; nt++) {
            int m = m0 + warp_m + mt * 16 + g;
            int n = n0 + warp_n + nt * 8 + t * 2;
            *(float2*)&Y[(size_t)m * DD + n]       = make_float2(acc[mt][nt][0], acc[mt][nt][1]);
            *(float2*)&Y[(size_t)(m + 8) * DD + n] = make_float2(acc[mt][nt][2], acc[mt][nt][3]);
        }
}

// ---------------- 1024-point complex FFT (radix-4 Stockham, shared memory) ----
__device__ __forceinline__ float2 cadd(float2 a, float2 b) { return make_float2(a.x + b.x, a.y + b.y); }
__device__ __forceinline__ float2 csub(float2 a, float2 b) { return make_float2(a.x - b.x, a.y - b.y); }
__device__ __forceinline__ float2 cmul(float2 a, float2 b) {
    return make_float2(a.x * b.x - a.y * b.y, a.x * b.y + a.y * b.x);
}

// one radix-4 Stockham stage; M = stride (compile-time), 256 butterflies, 128 thr
template<int M>
__device__ __forceinline__ void r4stage(const float2* __restrict__ x, float2* __restrict__ y, int t)
{
#pragma unroll
    for (int q = 0; q < 2; q++) {
        int bf = t + q * 128;          // 0..255
        int j = bf / M;                // compile-time M -> shift
        int k = bf - j * M;
        float2 c0 = x[k + j * M];
        float2 c1 = x[k + j * M + 256];
        float2 c2 = x[k + j * M + 512];
        float2 c3 = x[k + j * M + 768];
        float2 t0 = cadd(c0, c2);
        float2 t1 = csub(c0, c2);
        float2 t2 = cadd(c1, c3);
        float2 d  = csub(c1, c3);
        float2 t3 = make_float2(d.y, -d.x);   // -i * d
        float ang = -(2.0f * (float)CUDART_PI_F / 1024.0f) * (float)(j * M);
        float sn, cs;
        __sincosf(ang, &sn, &cs);
        float2 w1 = make_float2(cs, sn);
        float2 w2 = cmul(w1, w1);
        float2 w3 = cmul(w1, w2);
        int o = k + 4 * j * M;
        y[o]         = cadd(t0, t2);
        y[o + M]     = cmul(w1, cadd(t1, t3));
        y[o + 2 * M] = cmul(w2, csub(t0, t2));
        y[o + 3 * M] = cmul(w3, csub(t1, t3));
    }
    __syncthreads();
}

// full 1024-pt FFT: input in A (synced), result in B
__device__ __forceinline__ void fft1024_r4(float2* A, float2* B, int t)
{
    r4stage<1>(A, B, t);
    r4stage<4>(B, A, t);
    r4stage<16>(A, B, t);
    r4stage<64>(B, A, t);
    r4stage<256>(A, B, t);
}

__global__ __launch_bounds__(128) void fft_fwd()
{
    __shared__ float2 bufA[1024];
    __shared__ float2 bufB[1024];
    const int which = blockIdx.y;
    const int row = blockIdx.x;
    const float* __restrict__ src = &g_qkv[which][row][0];
    float2* __restrict__ dst = &g_spec[which][(size_t)row * DD];
    const int t = threadIdx.x;
#pragma unroll
    for (int i = 0; i < 8; i++) {
        int idx = t + i * 128;
        bufA[idx] = make_float2(src[idx], 0.f);
    }
    __syncthreads();
    fft1024_r4(bufA, bufB, t);
#pragma unroll
    for (int i = 0; i < 8; i++) {
        int idx = t + i * 128;
        dst[idx] = bufB[idx];
    }
}

__global__ __launch_bounds__(128) void fft_inv(float* __restrict__ out)
{
    __shared__ float2 bufA[1024];
    __shared__ float2 bufB[1024];
    const int row = blockIdx.x;
    const float2* __restrict__ src = &g_spec[0][(size_t)row * DD];
    float* __restrict__ dst = &out[(size_t)row * DD];
    const int t = threadIdx.x;
#pragma unroll
    for (int i = 0; i < 8; i++) {
        int idx = t + i * 128;
        float2 v = src[idx];
        bufA[idx] = make_float2(v.x, -v.y);
    }
    __syncthreads();
    fft1024_r4(bufA, bufB, t);
    const float invn = 1.f / 1024.f;
#pragma unroll
    for (int i = 0; i < 8; i++) {
        int idx = t + i * 128;
        dst[idx] = bufB[idx].x * invn;
    }
}

// ---------------- causal scan of fk*fv, unbind with conj(fq) -----------------
__global__ __launch_bounds__(128) void scanA()
{
    const int chunk = blockIdx.x;
    const int dt = blockIdx.y;
    const int b = blockIdx.z;
    const int d = dt * 128 + threadIdx.x;
    size_t base = ((size_t)b * SS + (size_t)chunk * CHUNKLEN) * DD + d;
    float2 acc = make_float2(0.f, 0.f);
#pragma unroll 4
    for (int s = 0; s < CHUNKLEN; s++) {
        float2 fk = g_spec[1][base + (size_t)s * DD];
        float2 fv = g_spec[2][base + (size_t)s * DD];
        acc.x += fk.x * fv.x - fk.y * fv.y;
        acc.y += fk.x * fv.y + fk.y * fv.x;
    }
    g_chunk[b][chunk][d] = acc;
}

__global__ __launch_bounds__(128) void scanC()
{
    const int chunk = blockIdx.x;
    const int dt = blockIdx.y;
    const int b = blockIdx.z;
    const int d = dt * 128 + threadIdx.x;
    size_t base = ((size_t)b * SS + (size_t)chunk * CHUNKLEN) * DD + d;
    float2 acc = make_float2(0.f, 0.f);
    for (int c = 0; c < chunk; c++) {
        float2 p = g_chunk[b][c][d];
        acc.x += p.x; acc.y += p.y;
    }
#pragma unroll 4
    for (int s = 0; s < CHUNKLEN; s++) {
        float2 fk = g_spec[1][base + (size_t)s * DD];
        float2 fv = g_spec[2][base + (size_t)s * DD];
        acc.x += fk.x * fv.x - fk.y * fv.y;
        acc.y += fk.x * fv.y + fk.y * fv.x;
        float2 fq = g_spec[0][base + (size_t)s * DD];
        float2 o = make_float2(acc.x * fq.x + acc.y * fq.y,
                               acc.y * fq.x - acc.x * fq.y);
        g_spec[0][base + (size_t)s * DD] = o;
    }
}

// ---------------- launch ------------------------------------------------------
extern "C" void kernel_launch(void* const* d_in, const int* in_sizes, int n_in,
                              void* d_out, int out_size)
{
    const float* x  = (const float*)d_in[0];
    const float* Wq = (const float*)d_in[1];
    const float* Wk = (const float*)d_in[2];
    const float* Wv = (const float*)d_in[3];
    float* out = (float*)d_out;

    split_x_k<<<(MM * DD) / 1024, 256>>>(x);
    split_w_k<<<dim3((DD * DD) / 1024, 3), 256>>>(Wq, Wk, Wv);

    cudaFuncSetAttribute(gemm_hmma, cudaFuncAttributeMaxDynamicSharedMemorySize, GEMM_SMEM_BYTES);
    gemm_hmma<<<dim3(DD / NT, MM / MT, 3), 256, GEMM_SMEM_BYTES>>>();

    fft_fwd<<<dim3(MM, 3), 128>>>();

    dim3 sgrid(NCHUNK, DD / 128, BB);
    scanA<<<sgrid, 128>>>();
    scanC<<<sgrid, 128>>>();

    fft_inv<<<MM, 128>>>(out);
}